// round 1
// baseline (speedup 1.0000x reference)
#include <cuda_runtime.h>

#define DIM    1024
#define NHEADS 16
#define HDIM   64
#define BATCH  2
#define SEQ    2048
#define BH     (BATCH * NHEADS)     // 32
#define MROWS  (BATCH * SEQ)        // 4096

// Scratch (static device globals; no runtime allocation allowed)
__device__ float g_Q [BH * SEQ * HDIM];   // [b,h,q,d]
__device__ float g_K [BH * SEQ * HDIM];
__device__ float g_V [BH * SEQ * HDIM];
__device__ float g_AO[MROWS * DIM];       // attention output, [b,q, h*64+d]

// ---------------------------------------------------------------------------
// GEMM: C[M,N] = A[M,K] @ B[N,K]^T   (B row-major [N,K], i.e. y = x @ W^T)
// MODE 0: scatter result into g_Q/g_K/g_V ([b,h,q,d] layout), A = Aext
// MODE 1: C[m,n] = acc + bias[n], A = g_AO
// 128x128 tile, BK=16, 8x8 microtile, 256 threads.
// ---------------------------------------------------------------------------
template <int MODE>
__global__ __launch_bounds__(256)
void gemm_kernel(const float* __restrict__ Aext,
                 const float* __restrict__ B,
                 const float* __restrict__ bias,
                 float* __restrict__ C,
                 int M, int N, int K)
{
    __shared__ float As[16][132];
    __shared__ float Bs[16][132];

    const int tid = threadIdx.x;
    const int tx  = tid & 15;
    const int ty  = tid >> 4;
    const int m0  = blockIdx.y * 128;
    const int n0  = blockIdx.x * 128;

    const float* A = (MODE == 0) ? Aext : g_AO;

    const float* Ab = A + (size_t)m0 * K;
    const float* Bb = B + (size_t)n0 * K;

    float acc[8][8] = {};

    for (int k0 = 0; k0 < K; k0 += 16) {
        #pragma unroll
        for (int i = 0; i < 2; i++) {
            int lin = tid + i * 256;           // 0..511
            int row = lin >> 2;                // 0..127
            int kc  = (lin & 3) << 2;          // 0,4,8,12
            float4 va = *(const float4*)(Ab + (size_t)row * K + k0 + kc);
            As[kc + 0][row] = va.x;
            As[kc + 1][row] = va.y;
            As[kc + 2][row] = va.z;
            As[kc + 3][row] = va.w;
            float4 vb = *(const float4*)(Bb + (size_t)row * K + k0 + kc);
            Bs[kc + 0][row] = vb.x;
            Bs[kc + 1][row] = vb.y;
            Bs[kc + 2][row] = vb.z;
            Bs[kc + 3][row] = vb.w;
        }
        __syncthreads();

        #pragma unroll
        for (int k = 0; k < 16; k++) {
            float a[8], b[8];
            #pragma unroll
            for (int i = 0; i < 8; i++) a[i] = As[k][ty * 8 + i];
            #pragma unroll
            for (int j = 0; j < 8; j++) b[j] = Bs[k][tx * 8 + j];
            #pragma unroll
            for (int i = 0; i < 8; i++)
                #pragma unroll
                for (int j = 0; j < 8; j++)
                    acc[i][j] = fmaf(a[i], b[j], acc[i][j]);
        }
        __syncthreads();
    }

    if (MODE == 0) {
        // scatter into Q/K/V: n = s*1024 + h*64 + d ; m = b*2048 + q
        #pragma unroll
        for (int i = 0; i < 8; i++) {
            int m  = m0 + ty * 8 + i;
            int b_ = m >> 11;
            int q  = m & 2047;
            #pragma unroll
            for (int j = 0; j < 8; j++) {
                int n = n0 + tx * 8 + j;
                int s = n >> 10;
                int r = n & 1023;
                int h = r >> 6;
                int d = r & 63;
                float* dst = (s == 0) ? g_Q : (s == 1) ? g_K : g_V;
                dst[(((size_t)(b_ * NHEADS + h)) * SEQ + q) * HDIM + d] = acc[i][j];
            }
        }
    } else {
        #pragma unroll
        for (int i = 0; i < 8; i++) {
            int m = m0 + ty * 8 + i;
            #pragma unroll
            for (int j = 0; j < 8; j += 4) {
                int n = n0 + tx * 8 + j;
                float4 v;
                v.x = acc[i][j + 0] + bias[n + 0];
                v.y = acc[i][j + 1] + bias[n + 1];
                v.z = acc[i][j + 2] + bias[n + 2];
                v.w = acc[i][j + 3] + bias[n + 3];
                *(float4*)(C + (size_t)m * N + n) = v;
            }
        }
    }
}

// ---------------------------------------------------------------------------
// Flash attention, fp32. One block = 64 query rows of one (b,h).
// 256 threads, 16x16 grid, 4x4 microtiles. Softmax stats fully in registers
// (row groups = 16-lane shuffle groups). SMEM = 48KB static:
//   Qt  [64][64]  Q^T, swizzled: element (q,d) at Qt[d][q ^ (d&60)]
//   KS  [64][64]  K^T (same swizzle) during QK^T; reused for P (swizzle
//                 col ^ ((q&7)<<2)) during PV
//   Vs  [64][64]  natural [k][d]
// ---------------------------------------------------------------------------
__global__ __launch_bounds__(256)
void flash_kernel()
{
    __shared__ float Qt[64][64];
    __shared__ float KS[64][64];
    __shared__ float Vs[64][64];

    const int tid = threadIdx.x;
    const int tx  = tid & 15;
    const int ty  = tid >> 4;
    const int bh  = blockIdx.y;
    const int q0  = blockIdx.x * 64;
    const size_t base = (size_t)bh * SEQ * HDIM;

    // Load Q tile transposed + swizzled
    #pragma unroll
    for (int it = 0; it < 4; it++) {
        int lin = tid + it * 256;
        int r   = lin >> 4;                 // q row 0..63
        int dc  = (lin & 15) << 2;          // d 0,4,...,60
        float4 v = *(const float4*)(g_Q + base + (size_t)(q0 + r) * HDIM + dc);
        int c = r ^ dc;                     // dc multiple of 4 -> dc == (d&60)
        Qt[dc + 0][c] = v.x;
        Qt[dc + 1][c] = v.y;
        Qt[dc + 2][c] = v.z;
        Qt[dc + 3][c] = v.w;
    }

    float m_i[4], l_i[4];
    float o[4][4] = {};
    #pragma unroll
    for (int i = 0; i < 4; i++) { m_i[i] = -1e30f; l_i[i] = 0.f; }

    __syncthreads();

    const float scale = 0.125f;   // HDIM^-0.5

    for (int k0 = 0; k0 < SEQ; k0 += 64) {
        // Load K tile (transposed+swizzled) and V tile (natural)
        #pragma unroll
        for (int it = 0; it < 4; it++) {
            int lin = tid + it * 256;
            int r   = lin >> 4;
            int dc  = (lin & 15) << 2;
            float4 kv = *(const float4*)(g_K + base + (size_t)(k0 + r) * HDIM + dc);
            int c = r ^ dc;
            KS[dc + 0][c] = kv.x;
            KS[dc + 1][c] = kv.y;
            KS[dc + 2][c] = kv.z;
            KS[dc + 3][c] = kv.w;
            float4 vv = *(const float4*)(g_V + base + (size_t)(k0 + r) * HDIM + dc);
            *(float4*)&Vs[r][dc] = vv;
        }
        __syncthreads();

        // S = Q K^T  (4x4 per thread; rows ty*4+i, cols tx*4+j)
        float s[4][4] = {};
        #pragma unroll
        for (int k = 0; k < 64; k++) {
            int swz = k & 60;
            float a[4], b[4];
            *(float4*)a = *(const float4*)&Qt[k][(ty * 4) ^ swz];
            *(float4*)b = *(const float4*)&KS[k][(tx * 4) ^ swz];
            #pragma unroll
            for (int i = 0; i < 4; i++)
                #pragma unroll
                for (int j = 0; j < 4; j++)
                    s[i][j] = fmaf(a[i], b[j], s[i][j]);
        }

        // Register-resident online softmax (row reduce across 16-lane groups)
        float alpha[4];
        #pragma unroll
        for (int i = 0; i < 4; i++) {
            #pragma unroll
            for (int j = 0; j < 4; j++) s[i][j] *= scale;
            float mx = fmaxf(fmaxf(s[i][0], s[i][1]), fmaxf(s[i][2], s[i][3]));
            #pragma unroll
            for (int off = 1; off < 16; off <<= 1)
                mx = fmaxf(mx, __shfl_xor_sync(0xffffffffu, mx, off));
            float mnew = fmaxf(m_i[i], mx);
            alpha[i] = __expf(m_i[i] - mnew);
            m_i[i]   = mnew;
            float sum = 0.f;
            #pragma unroll
            for (int j = 0; j < 4; j++) {
                float p = __expf(s[i][j] - mnew);
                s[i][j] = p;
                sum += p;
            }
            #pragma unroll
            for (int off = 1; off < 16; off <<= 1)
                sum += __shfl_xor_sync(0xffffffffu, sum, off);
            l_i[i] = l_i[i] * alpha[i] + sum;
        }

        __syncthreads();   // everyone done reading KS as K

        // Write P into KS (row-dependent swizzle), rescale O
        #pragma unroll
        for (int i = 0; i < 4; i++) {
            int row = ty * 4 + i;
            int g   = (row & 7) << 2;
            *(float4*)&KS[row][(tx * 4) ^ g] = *(float4*)s[i];
            #pragma unroll
            for (int j = 0; j < 4; j++) o[i][j] *= alpha[i];
        }

        __syncthreads();   // P visible

        // O += P V   (rows ty*4+i, d cols tx*4+j, reduce over k)
        #pragma unroll
        for (int k = 0; k < 64; k++) {
            float p[4], vv[4];
            #pragma unroll
            for (int i = 0; i < 4; i++) {
                int row = ty * 4 + i;
                p[i] = KS[row][k ^ ((row & 7) << 2)];
            }
            *(float4*)vv = *(const float4*)&Vs[k][tx * 4];
            #pragma unroll
            for (int i = 0; i < 4; i++)
                #pragma unroll
                for (int j = 0; j < 4; j++)
                    o[i][j] = fmaf(p[i], vv[j], o[i][j]);
        }

        __syncthreads();   // before next iteration overwrites KS/Vs
    }

    // Epilogue: normalize, write to g_AO as [b, q, h*64+d]
    const int b_ = bh >> 4;
    const int h  = bh & 15;
    float* Op = g_AO + ((size_t)b_ * SEQ + q0) * DIM + h * HDIM;
    #pragma unroll
    for (int i = 0; i < 4; i++) {
        float inv = 1.f / l_i[i];
        float4 v;
        v.x = o[i][0] * inv;
        v.y = o[i][1] * inv;
        v.z = o[i][2] * inv;
        v.w = o[i][3] * inv;
        *(float4*)&Op[(size_t)(ty * 4 + i) * DIM + tx * 4] = v;
    }
}

// ---------------------------------------------------------------------------
extern "C" void kernel_launch(void* const* d_in, const int* in_sizes, int n_in,
                              void* d_out, int out_size)
{
    const float* x      = (const float*)d_in[0];   // [2,2048,1024]
    const float* w_qkv  = (const float*)d_in[1];   // [3072,1024]
    const float* w_proj = (const float*)d_in[2];   // [1024,1024]
    const float* b_proj = (const float*)d_in[3];   // [1024]
    float* out = (float*)d_out;                    // [2,2048,1024]

    // 1) QKV projection, scatter to Q/K/V [b,h,q,d]
    gemm_kernel<0><<<dim3(3 * DIM / 128, MROWS / 128), 256>>>(
        x, w_qkv, nullptr, nullptr, MROWS, 3 * DIM, DIM);

    // 2) Attention per (b,h), 64 queries per block
    flash_kernel<<<dim3(SEQ / 64, BH), 256>>>();

    // 3) Output projection + bias
    gemm_kernel<1><<<dim3(DIM / 128, MROWS / 128), 256>>>(
        nullptr, w_proj, b_proj, out, MROWS, DIM, DIM);
}

// round 3
// speedup vs baseline: 2.4762x; 2.4762x over previous
#include <cuda_runtime.h>
#include <cuda_bf16.h>
#include <cstdint>

#define DIM    1024
#define NHEADS 16
#define HDIM   64
#define BATCH  2
#define SEQ    2048
#define MROWS  (BATCH * SEQ)        // 4096

// Scratch (static device globals; no runtime allocation allowed)
__device__ float g_QKV[(size_t)MROWS * 3 * DIM];  // [b*2048+q][3072], n = s*1024+h*64+d
__device__ float g_AO [(size_t)MROWS * DIM];      // [b*2048+q][1024], n = h*64+d

// ---------------------------------------------------------------------------
// Helpers
// ---------------------------------------------------------------------------
__device__ __forceinline__ uint32_t smem_u32(const void* p) {
    uint32_t a;
    asm("{ .reg .u64 t; cvta.to.shared.u64 t, %1; cvt.u32.u64 %0, t; }" : "=r"(a) : "l"(p));
    return a;
}

__device__ __forceinline__ void ldsm4(uint32_t r[4], uint32_t addr) {
    asm volatile("ldmatrix.sync.aligned.m8n8.x4.shared.b16 {%0,%1,%2,%3}, [%4];"
                 : "=r"(r[0]), "=r"(r[1]), "=r"(r[2]), "=r"(r[3]) : "r"(addr));
}
__device__ __forceinline__ void ldsm4t(uint32_t r[4], uint32_t addr) {
    asm volatile("ldmatrix.sync.aligned.m8n8.x4.trans.shared.b16 {%0,%1,%2,%3}, [%4];"
                 : "=r"(r[0]), "=r"(r[1]), "=r"(r[2]), "=r"(r[3]) : "r"(addr));
}

__device__ __forceinline__ void mma_bf(float c[4], const uint32_t a[4], const uint32_t b[2]) {
    asm volatile(
        "mma.sync.aligned.m16n8k16.row.col.f32.bf16.bf16.f32 "
        "{%0,%1,%2,%3}, {%4,%5,%6,%7}, {%8,%9}, {%0,%1,%2,%3};"
        : "+f"(c[0]), "+f"(c[1]), "+f"(c[2]), "+f"(c[3])
        : "r"(a[0]), "r"(a[1]), "r"(a[2]), "r"(a[3]), "r"(b[0]), "r"(b[1]));
}

__device__ __forceinline__ uint32_t packbf(float x, float y) {
    unsigned short ux = __bfloat16_as_ushort(__float2bfloat16(x));
    unsigned short uy = __bfloat16_as_ushort(__float2bfloat16(y));
    return (uint32_t)ux | ((uint32_t)uy << 16);
}

// fp32x4 -> hi pair-regs + lo pair-regs (hi/lo bf16 split)
__device__ __forceinline__ void split4(float4 v, uint32_t& h0, uint32_t& h1,
                                       uint32_t& l0, uint32_t& l1) {
    float hx = __bfloat162float(__float2bfloat16(v.x));
    float hy = __bfloat162float(__float2bfloat16(v.y));
    float hz = __bfloat162float(__float2bfloat16(v.z));
    float hw = __bfloat162float(__float2bfloat16(v.w));
    h0 = packbf(v.x, v.y);
    h1 = packbf(v.z, v.w);
    l0 = packbf(v.x - hx, v.y - hy);
    l1 = packbf(v.z - hz, v.w - hw);
}

// ---------------------------------------------------------------------------
// GEMM: C[M,N] = A[M,K] @ B[N,K]^T   (bf16 hi/lo 3-MMA split, fp32 accum)
// block 128x128, BK=32, 256 threads (8 warps, warp tile 64x32)
// smem rows: 64 bf16 = 8 x 16B chunks; logical chunks 0-3 = hi(k0..31),
// 4-7 = lo; physical chunk = logical ^ (row&7)  -> conflict-free ldmatrix.
// EPI: 0 plain store, 1 add bias.
// ---------------------------------------------------------------------------
template <int EPI>
__global__ __launch_bounds__(256)
void mm_bf16(const float* __restrict__ A, const float* __restrict__ Bw,
             const float* __restrict__ bias, float* __restrict__ C,
             int N, int K)
{
    __shared__ uint32_t sA[4096];   // 16KB: [128 rows][32 u32]
    __shared__ uint32_t sB[4096];

    const int tid = threadIdx.x, lane = tid & 31, wid = tid >> 5;
    const int m0 = blockIdx.y * 128, n0 = blockIdx.x * 128;
    const int wm = (wid & 1) * 64, wn = (wid >> 1) * 32;
    const uint32_t aBase = smem_u32(sA), bBase = smem_u32(sB);

    const int arow = lane & 15;                 // A-style ldmatrix row pattern
    const int aco  = lane >> 4;
    const int brow = (lane & 7) | ((lane & 16) >> 1);   // B-style pattern
    const int bco  = (lane & 8) >> 3;

    float acc[4][4][4] = {};

    for (int k0 = 0; k0 < K; k0 += 32) {
        #pragma unroll
        for (int it = 0; it < 4; it++) {
            int idx = tid + it * 256;            // 0..1023
            int row = idx >> 3, c4 = idx & 7;    // float4 col (k = c4*4)
            int ch = c4 >> 1, hf = c4 & 1;
            int pH = ch ^ (row & 7), pL = (ch | 4) ^ (row & 7);
            uint32_t h0, h1, l0, l1;
            float4 va = *(const float4*)(A + (size_t)(m0 + row) * K + k0 + c4 * 4);
            split4(va, h0, h1, l0, l1);
            sA[row * 32 + pH * 4 + hf * 2 + 0] = h0;
            sA[row * 32 + pH * 4 + hf * 2 + 1] = h1;
            sA[row * 32 + pL * 4 + hf * 2 + 0] = l0;
            sA[row * 32 + pL * 4 + hf * 2 + 1] = l1;
            float4 vb = *(const float4*)(Bw + (size_t)(n0 + row) * K + k0 + c4 * 4);
            split4(vb, h0, h1, l0, l1);
            sB[row * 32 + pH * 4 + hf * 2 + 0] = h0;
            sB[row * 32 + pH * 4 + hf * 2 + 1] = h1;
            sB[row * 32 + pL * 4 + hf * 2 + 0] = l0;
            sB[row * 32 + pL * 4 + hf * 2 + 1] = l1;
        }
        __syncthreads();

        #pragma unroll
        for (int kk = 0; kk < 2; kk++) {
            uint32_t aH[4][4], aL[4][4], bH[2][4], bL[2][4];
            #pragma unroll
            for (int mt = 0; mt < 4; mt++) {
                int r = wm + mt * 16 + arow;
                int cH = (kk * 2 + aco) ^ (r & 7);
                int cL = (kk * 2 + aco + 4) ^ (r & 7);
                ldsm4(aH[mt], aBase + r * 128 + cH * 16);
                ldsm4(aL[mt], aBase + r * 128 + cL * 16);
            }
            #pragma unroll
            for (int g = 0; g < 2; g++) {
                int r = wn + g * 16 + brow;
                int cH = (kk * 2 + bco) ^ (r & 7);
                int cL = (kk * 2 + bco + 4) ^ (r & 7);
                ldsm4(bH[g], bBase + r * 128 + cH * 16);
                ldsm4(bL[g], bBase + r * 128 + cL * 16);
            }
            #pragma unroll
            for (int mt = 0; mt < 4; mt++)
                #pragma unroll
                for (int nt = 0; nt < 4; nt++) {
                    const uint32_t* bh = &bH[nt >> 1][(nt & 1) * 2];
                    const uint32_t* bl = &bL[nt >> 1][(nt & 1) * 2];
                    mma_bf(acc[mt][nt], aH[mt], bh);
                    mma_bf(acc[mt][nt], aH[mt], bl);
                    mma_bf(acc[mt][nt], aL[mt], bh);
                }
        }
        __syncthreads();
    }

    const int r = lane >> 2, j = (lane & 3) * 2;
    #pragma unroll
    for (int mt = 0; mt < 4; mt++) {
        int mA = m0 + wm + mt * 16 + r;
        #pragma unroll
        for (int nt = 0; nt < 4; nt++) {
            int c = n0 + wn + nt * 8 + j;
            float b0 = 0.f, b1 = 0.f;
            if (EPI) { b0 = bias[c]; b1 = bias[c + 1]; }
            *(float2*)(C + (size_t)mA * N + c) =
                make_float2(acc[mt][nt][0] + b0, acc[mt][nt][1] + b1);
            *(float2*)(C + (size_t)(mA + 8) * N + c) =
                make_float2(acc[mt][nt][2] + b0, acc[mt][nt][3] + b1);
        }
    }
}

// ---------------------------------------------------------------------------
// Flash attention with HMMA (hi/lo split on Q,K,P,V).
// Block: 128 queries of one (b,h), 256 threads / 8 warps; warp owns 16 rows.
// 64-key tiles. Dynamic smem 64KB:
//   Qhi[128][64]bf16, Qlo, Khi[64][64], Klo, Vhi[64][64], Vlo
// u32 offsets: QH 0, QL 4096, KH 8192, KL 10240, VH 12288, VL 14336.
// ---------------------------------------------------------------------------
__global__ __launch_bounds__(256)
void flash_mma()
{
    extern __shared__ uint32_t sm[];
    const int tid = threadIdx.x, lane = tid & 31, w = tid >> 5;
    const int bh = blockIdx.y, b = bh >> 4, h = bh & 15;
    const int q0 = blockIdx.x * 128;
    const uint32_t base = smem_u32(sm);
    const uint32_t QH = 0, QL = 4096, KH = 8192, KL = 10240, VH = 12288, VL = 14336;

    const int arow = lane & 15;
    const int aco  = lane >> 4;
    const int brow = (lane & 7) | ((lane & 16) >> 1);
    const int bco  = (lane & 8) >> 3;

    const float* Qg = g_QKV + ((size_t)(b * SEQ + q0)) * 3072 + h * 64;
    const float* Kg = g_QKV + ((size_t)(b * SEQ)) * 3072 + 1024 + h * 64;
    const float* Vg = Kg + 1024;

    // Load Q tile (128 x 64) -> hi/lo smem
    #pragma unroll
    for (int it = 0; it < 8; it++) {
        int idx = tid + it * 256;              // 0..2047
        int row = idx >> 4, c4 = idx & 15;
        int ch = c4 >> 1, hf = c4 & 1, ph = ch ^ (row & 7);
        uint32_t h0, h1, l0, l1;
        float4 v = *(const float4*)(Qg + (size_t)row * 3072 + c4 * 4);
        split4(v, h0, h1, l0, l1);
        sm[QH + row * 32 + ph * 4 + hf * 2 + 0] = h0;
        sm[QH + row * 32 + ph * 4 + hf * 2 + 1] = h1;
        sm[QL + row * 32 + ph * 4 + hf * 2 + 0] = l0;
        sm[QL + row * 32 + ph * 4 + hf * 2 + 1] = l1;
    }

    float m_a = -1e30f, m_b = -1e30f, l_a = 0.f, l_b = 0.f;
    float o[8][4] = {};

    for (int s0 = 0; s0 < SEQ; s0 += 64) {
        // Load K and V tiles (64 x 64 each) -> hi/lo smem
        #pragma unroll
        for (int it = 0; it < 4; it++) {
            int idx = tid + it * 256;          // 0..1023
            int row = idx >> 4, c4 = idx & 15;
            int ch = c4 >> 1, hf = c4 & 1, ph = ch ^ (row & 7);
            uint32_t h0, h1, l0, l1;
            float4 v = *(const float4*)(Kg + (size_t)(s0 + row) * 3072 + c4 * 4);
            split4(v, h0, h1, l0, l1);
            sm[KH + row * 32 + ph * 4 + hf * 2 + 0] = h0;
            sm[KH + row * 32 + ph * 4 + hf * 2 + 1] = h1;
            sm[KL + row * 32 + ph * 4 + hf * 2 + 0] = l0;
            sm[KL + row * 32 + ph * 4 + hf * 2 + 1] = l1;
            float4 u = *(const float4*)(Vg + (size_t)(s0 + row) * 3072 + c4 * 4);
            split4(u, h0, h1, l0, l1);
            sm[VH + row * 32 + ph * 4 + hf * 2 + 0] = h0;
            sm[VH + row * 32 + ph * 4 + hf * 2 + 1] = h1;
            sm[VL + row * 32 + ph * 4 + hf * 2 + 0] = l0;
            sm[VL + row * 32 + ph * 4 + hf * 2 + 1] = l1;
        }
        __syncthreads();

        // S = Q K^T  (8 n8-tiles of keys, 4 k16 chunks of d)
        float s[8][4] = {};
        #pragma unroll
        for (int kk = 0; kk < 4; kk++) {
            uint32_t aH[4], aL[4];
            {
                int r = w * 16 + arow;
                int c = (kk * 2 + aco) ^ (r & 7);
                ldsm4(aH, base + QH * 4 + r * 128 + c * 16);
                ldsm4(aL, base + QL * 4 + r * 128 + c * 16);
            }
            uint32_t bH[4][4], bL[4][4];
            #pragma unroll
            for (int g = 0; g < 4; g++) {
                int r = g * 16 + brow;
                int c = (kk * 2 + bco) ^ (r & 7);
                ldsm4(bH[g], base + KH * 4 + r * 128 + c * 16);
                ldsm4(bL[g], base + KL * 4 + r * 128 + c * 16);
            }
            #pragma unroll
            for (int nt = 0; nt < 8; nt++) {
                const uint32_t* bh = &bH[nt >> 1][(nt & 1) * 2];
                const uint32_t* bl = &bL[nt >> 1][(nt & 1) * 2];
                mma_bf(s[nt], aH, bh);
                mma_bf(s[nt], aH, bl);
                mma_bf(s[nt], aL, bh);
            }
        }

        // Online softmax (rows r=lane>>2 and r+8; reduce over 4-lane groups)
        float mxa = -1e30f, mxb = -1e30f;
        #pragma unroll
        for (int nt = 0; nt < 8; nt++) {
            s[nt][0] *= 0.125f; s[nt][1] *= 0.125f;
            s[nt][2] *= 0.125f; s[nt][3] *= 0.125f;
            mxa = fmaxf(mxa, fmaxf(s[nt][0], s[nt][1]));
            mxb = fmaxf(mxb, fmaxf(s[nt][2], s[nt][3]));
        }
        mxa = fmaxf(mxa, __shfl_xor_sync(0xffffffffu, mxa, 1));
        mxa = fmaxf(mxa, __shfl_xor_sync(0xffffffffu, mxa, 2));
        mxb = fmaxf(mxb, __shfl_xor_sync(0xffffffffu, mxb, 1));
        mxb = fmaxf(mxb, __shfl_xor_sync(0xffffffffu, mxb, 2));
        float mna = fmaxf(m_a, mxa), mnb = fmaxf(m_b, mxb);
        float alA = __expf(m_a - mna), alB = __expf(m_b - mnb);
        m_a = mna; m_b = mnb;
        float suma = 0.f, sumb = 0.f;
        #pragma unroll
        for (int nt = 0; nt < 8; nt++) {
            s[nt][0] = __expf(s[nt][0] - mna); suma += s[nt][0];
            s[nt][1] = __expf(s[nt][1] - mna); suma += s[nt][1];
            s[nt][2] = __expf(s[nt][2] - mnb); sumb += s[nt][2];
            s[nt][3] = __expf(s[nt][3] - mnb); sumb += s[nt][3];
        }
        suma += __shfl_xor_sync(0xffffffffu, suma, 1);
        suma += __shfl_xor_sync(0xffffffffu, suma, 2);
        sumb += __shfl_xor_sync(0xffffffffu, sumb, 1);
        sumb += __shfl_xor_sync(0xffffffffu, sumb, 2);
        l_a = l_a * alA + suma;
        l_b = l_b * alB + sumb;
        #pragma unroll
        for (int dt = 0; dt < 8; dt++) {
            o[dt][0] *= alA; o[dt][1] *= alA;
            o[dt][2] *= alB; o[dt][3] *= alB;
        }

        // O += P V   (P fragments from registers; V via ldmatrix.trans)
        #pragma unroll
        for (int kc = 0; kc < 4; kc++) {
            uint32_t pH[4], pL[4];
            {
                float x0 = s[2*kc][0], x1 = s[2*kc][1], x2 = s[2*kc][2], x3 = s[2*kc][3];
                float y0 = s[2*kc+1][0], y1 = s[2*kc+1][1], y2 = s[2*kc+1][2], y3 = s[2*kc+1][3];
                pH[0] = packbf(x0, x1); pH[1] = packbf(x2, x3);
                pH[2] = packbf(y0, y1); pH[3] = packbf(y2, y3);
                float hx0 = __bfloat162float(__float2bfloat16(x0));
                float hx1 = __bfloat162float(__float2bfloat16(x1));
                float hx2 = __bfloat162float(__float2bfloat16(x2));
                float hx3 = __bfloat162float(__float2bfloat16(x3));
                float hy0 = __bfloat162float(__float2bfloat16(y0));
                float hy1 = __bfloat162float(__float2bfloat16(y1));
                float hy2 = __bfloat162float(__float2bfloat16(y2));
                float hy3 = __bfloat162float(__float2bfloat16(y3));
                pL[0] = packbf(x0 - hx0, x1 - hx1); pL[1] = packbf(x2 - hx2, x3 - hx3);
                pL[2] = packbf(y0 - hy0, y1 - hy1); pL[3] = packbf(y2 - hy2, y3 - hy3);
            }
            uint32_t vH[4][4], vL[4][4];
            #pragma unroll
            for (int g = 0; g < 4; g++) {
                int r = kc * 16 + arow;
                int c = (g * 2 + aco) ^ (r & 7);
                ldsm4t(vH[g], base + VH * 4 + r * 128 + c * 16);
                ldsm4t(vL[g], base + VL * 4 + r * 128 + c * 16);
            }
            #pragma unroll
            for (int dt = 0; dt < 8; dt++) {
                const uint32_t* vh = &vH[dt >> 1][(dt & 1) * 2];
                const uint32_t* vl = &vL[dt >> 1][(dt & 1) * 2];
                mma_bf(o[dt], pH, vh);
                mma_bf(o[dt], pH, vl);
                mma_bf(o[dt], pL, vh);
            }
        }
        __syncthreads();
    }

    // Epilogue: normalize, write fp32 to g_AO [m][1024]
    float ia = 1.f / l_a, ib = 1.f / l_b;
    int ra = q0 + w * 16 + (lane >> 2);
    float* Oa = g_AO + ((size_t)(b * SEQ) + ra) * 1024 + h * 64;
    float* Ob = Oa + 8 * 1024;
    #pragma unroll
    for (int dt = 0; dt < 8; dt++) {
        int c = dt * 8 + (lane & 3) * 2;
        *(float2*)(Oa + c) = make_float2(o[dt][0] * ia, o[dt][1] * ia);
        *(float2*)(Ob + c) = make_float2(o[dt][2] * ib, o[dt][3] * ib);
    }
}

// ---------------------------------------------------------------------------
extern "C" void kernel_launch(void* const* d_in, const int* in_sizes, int n_in,
                              void* d_out, int out_size)
{
    const float* x      = (const float*)d_in[0];   // [2,2048,1024]
    const float* w_qkv  = (const float*)d_in[1];   // [3072,1024]
    const float* w_proj = (const float*)d_in[2];   // [1024,1024]
    const float* b_proj = (const float*)d_in[3];   // [1024]
    float* out = (float*)d_out;                    // [2,2048,1024]

    void *pQKV, *pAO;
    cudaGetSymbolAddress(&pQKV, g_QKV);
    cudaGetSymbolAddress(&pAO, g_AO);

    cudaFuncSetAttribute(flash_mma, cudaFuncAttributeMaxDynamicSharedMemorySize, 65536);

    // 1) QKV projection: g_QKV[m][3072]
    mm_bf16<0><<<dim3(3 * DIM / 128, MROWS / 128), 256>>>(
        x, w_qkv, nullptr, (float*)pQKV, 3 * DIM, DIM);

    // 2) Attention: 128 queries/block per (b,h)
    flash_mma<<<dim3(SEQ / 128, BATCH * NHEADS), 256, 65536>>>();

    // 3) Output projection + bias
    mm_bf16<1><<<dim3(DIM / 128, MROWS / 128), 256>>>(
        (const float*)pAO, w_proj, b_proj, out, DIM, DIM);
}

// round 4
// speedup vs baseline: 3.0422x; 1.2286x over previous
#include <cuda_runtime.h>
#include <cuda_bf16.h>
#include <cstdint>

#define DIM    1024
#define NHEADS 16
#define HDIM   64
#define BATCH  2
#define SEQ    2048
#define MROWS  4096

// ---------------------------------------------------------------------------
// Packed bf16 hi/lo global scratch (u32 = 2 bf16, k-major pairs)
// ---------------------------------------------------------------------------
__device__ __align__(128) uint32_t g_xh [MROWS * 512], g_xl [MROWS * 512];
__device__ __align__(128) uint32_t g_wqh[3072 * 512],  g_wql[3072 * 512];
__device__ __align__(128) uint32_t g_wph[1024 * 512],  g_wpl[1024 * 512];
// QKV: [s_idx(3)][bh(32)][seq(2048)][32 u32]   (Q pre-scaled by 0.125)
__device__ __align__(128) uint32_t g_qkvh[3u * 2097152], g_qkvl[3u * 2097152];
__device__ __align__(128) uint32_t g_aoh[MROWS * 512], g_aol[MROWS * 512];

// ---------------------------------------------------------------------------
// Helpers
// ---------------------------------------------------------------------------
__device__ __forceinline__ uint32_t smem_u32(const void* p) {
    uint32_t a;
    asm("{ .reg .u64 t; cvta.to.shared.u64 t, %1; cvt.u32.u64 %0, t; }" : "=r"(a) : "l"(p));
    return a;
}
__device__ __forceinline__ void ldsm4(uint32_t r[4], uint32_t addr) {
    asm volatile("ldmatrix.sync.aligned.m8n8.x4.shared.b16 {%0,%1,%2,%3}, [%4];"
                 : "=r"(r[0]), "=r"(r[1]), "=r"(r[2]), "=r"(r[3]) : "r"(addr));
}
__device__ __forceinline__ void ldsm4t(uint32_t r[4], uint32_t addr) {
    asm volatile("ldmatrix.sync.aligned.m8n8.x4.trans.shared.b16 {%0,%1,%2,%3}, [%4];"
                 : "=r"(r[0]), "=r"(r[1]), "=r"(r[2]), "=r"(r[3]) : "r"(addr));
}
__device__ __forceinline__ void mma_bf(float c[4], const uint32_t a[4], const uint32_t b[2]) {
    asm volatile(
        "mma.sync.aligned.m16n8k16.row.col.f32.bf16.bf16.f32 "
        "{%0,%1,%2,%3}, {%4,%5,%6,%7}, {%8,%9}, {%0,%1,%2,%3};"
        : "+f"(c[0]), "+f"(c[1]), "+f"(c[2]), "+f"(c[3])
        : "r"(a[0]), "r"(a[1]), "r"(a[2]), "r"(a[3]), "r"(b[0]), "r"(b[1]));
}
__device__ __forceinline__ uint32_t packbf(float x, float y) {
    unsigned short ux = __bfloat16_as_ushort(__float2bfloat16(x));
    unsigned short uy = __bfloat16_as_ushort(__float2bfloat16(y));
    return (uint32_t)ux | ((uint32_t)uy << 16);
}
__device__ __forceinline__ void hilo2(float x, float y, uint32_t& hi, uint32_t& lo) {
    float hx = __bfloat162float(__float2bfloat16(x));
    float hy = __bfloat162float(__float2bfloat16(y));
    hi = packbf(x, y);
    lo = packbf(x - hx, y - hy);
}
__device__ __forceinline__ void cpa16(uint32_t dst, const void* src) {
    asm volatile("cp.async.cg.shared.global [%0], [%1], 16;" :: "r"(dst), "l"(src));
}
#define CP_COMMIT() asm volatile("cp.async.commit_group;" ::: "memory")
#define CP_WAIT(n)  asm volatile("cp.async.wait_group %0;" :: "n"(n) : "memory")

// ---------------------------------------------------------------------------
// Split fp32 [rows][1024] -> packed hi/lo u32 [rows][512]
// ---------------------------------------------------------------------------
__global__ __launch_bounds__(256)
void split_k(const float* __restrict__ in, uint32_t* __restrict__ hi,
             uint32_t* __restrict__ lo, int n4)
{
    int g = blockIdx.x * 256 + threadIdx.x;
    if (g >= n4) return;
    float4 v = ((const float4*)in)[g];
    uint32_t h0, l0, h1, l1;
    hilo2(v.x, v.y, h0, l0);
    hilo2(v.z, v.w, h1, l1);
    ((uint2*)hi)[g] = make_uint2(h0, h1);
    ((uint2*)lo)[g] = make_uint2(l0, l1);
}

// ---------------------------------------------------------------------------
// GEMM: C[M,N] = A[M,K] @ B[N,K]^T, bf16 hi/lo 3-MMA, cp.async 3-stage.
// Block 128x128, BK=32, 256 thr (8 warps, 64x32 warp tile).
// smem per stage 32KB: A[128][128B], B[128][128B]; row = 8x16B chunks
// (0-3 hi, 4-7 lo), phys chunk = logical ^ (row&7).
// EPI 0: split-store into g_qkvh/l (Q scaled by 0.125). EPI 1: fp32 + bias.
// ---------------------------------------------------------------------------
template <int EPI>
__global__ __launch_bounds__(256)
void mm2(const uint32_t* __restrict__ Ah, const uint32_t* __restrict__ Al,
         const uint32_t* __restrict__ Bh, const uint32_t* __restrict__ Bl,
         const float* __restrict__ bias, float* __restrict__ Cout,
         uint32_t* __restrict__ qh, uint32_t* __restrict__ ql,
         int N, int K)
{
    extern __shared__ __align__(128) uint32_t sm[];
    const int tid = threadIdx.x, lane = tid & 31, wid = tid >> 5;
    const int m0 = blockIdx.y * 128, n0 = blockIdx.x * 128;
    const int wm = (wid & 1) * 64, wn = (wid >> 1) * 32;
    const uint32_t base = smem_u32(sm);
    const int T  = K >> 5;
    const int KC = K >> 3;   // 16B chunks per row

    const int arow = lane & 15, aco = lane >> 4;
    const int brow = (lane & 7) | ((lane & 16) >> 1), bco = (lane & 8) >> 3;

    auto issue = [&](int t) {
        int st  = t % 3;
        int kc0 = t << 2;
        #pragma unroll
        for (int it = 0; it < 8; it++) {
            int idx = tid + it * 256;              // 0..2047 (A first, then B)
            int row = (idx >> 3) & 127;
            int ch  = idx & 7;
            bool isB = idx >= 1024;
            const uint32_t* sp = isB ? (ch < 4 ? Bh : Bl) : (ch < 4 ? Ah : Al);
            int grow = (isB ? n0 : m0) + row;
            const void* src = sp + ((size_t)grow * KC + kc0 + (ch & 3)) * 4;
            uint32_t dst = base + st * 32768 + (isB ? 16384 : 0)
                         + row * 128 + ((ch ^ (row & 7)) * 16);
            cpa16(dst, src);
        }
    };

    float acc[4][4][4] = {};

    issue(0); CP_COMMIT();
    issue(1); CP_COMMIT();

    for (int t = 0; t < T; t++) {
        if (t + 2 < T) issue(t + 2);
        CP_COMMIT();
        CP_WAIT(2);
        __syncthreads();

        const uint32_t aOff = base + (t % 3) * 32768;
        const uint32_t bOff = aOff + 16384;
        #pragma unroll
        for (int kk = 0; kk < 2; kk++) {
            uint32_t aH[4][4], aL[4][4], bH[2][4], bL[2][4];
            #pragma unroll
            for (int mt = 0; mt < 4; mt++) {
                int r = wm + mt * 16 + arow;
                int c = (kk * 2 + aco) ^ (r & 7);
                ldsm4(aH[mt], aOff + r * 128 + c * 16);
                ldsm4(aL[mt], aOff + r * 128 + (c ^ 4) * 16);
            }
            #pragma unroll
            for (int g = 0; g < 2; g++) {
                int r = wn + g * 16 + brow;
                int c = (kk * 2 + bco) ^ (r & 7);
                ldsm4(bH[g], bOff + r * 128 + c * 16);
                ldsm4(bL[g], bOff + r * 128 + (c ^ 4) * 16);
            }
            #pragma unroll
            for (int mt = 0; mt < 4; mt++)
                #pragma unroll
                for (int nt = 0; nt < 4; nt++) {
                    const uint32_t* bh = &bH[nt >> 1][(nt & 1) * 2];
                    const uint32_t* bl = &bL[nt >> 1][(nt & 1) * 2];
                    mma_bf(acc[mt][nt], aH[mt], bh);
                    mma_bf(acc[mt][nt], aH[mt], bl);
                    mma_bf(acc[mt][nt], aL[mt], bh);
                }
        }
        __syncthreads();
    }

    const int r = lane >> 2, j = (lane & 3) * 2;
    if (EPI == 0) {
        const int sidx = n0 >> 10;
        const float qs = (sidx == 0) ? 0.125f : 1.0f;
        uint32_t* H = qh + (size_t)sidx * 2097152;
        uint32_t* L = ql + (size_t)sidx * 2097152;
        #pragma unroll
        for (int mt = 0; mt < 4; mt++) {
            int mA = m0 + wm + mt * 16 + r;
            int b  = mA >> 11, q = mA & 2047;
            #pragma unroll
            for (int nt = 0; nt < 4; nt++) {
                int n = n0 + wn + nt * 8 + j;
                int rin = n & 1023, h = rin >> 6, d = rin & 63;
                size_t o1 = (((size_t)(b * 16 + h)) * 2048 + q) * 32 + (d >> 1);
                uint32_t hh, ll;
                hilo2(acc[mt][nt][0] * qs, acc[mt][nt][1] * qs, hh, ll);
                H[o1] = hh; L[o1] = ll;
                hilo2(acc[mt][nt][2] * qs, acc[mt][nt][3] * qs, hh, ll);
                H[o1 + 8 * 32] = hh; L[o1 + 8 * 32] = ll;
            }
        }
    } else {
        #pragma unroll
        for (int mt = 0; mt < 4; mt++) {
            int mA = m0 + wm + mt * 16 + r;
            #pragma unroll
            for (int nt = 0; nt < 4; nt++) {
                int c = n0 + wn + nt * 8 + j;
                float b0 = bias[c], b1 = bias[c + 1];
                *(float2*)(Cout + (size_t)mA * N + c) =
                    make_float2(acc[mt][nt][0] + b0, acc[mt][nt][1] + b1);
                *(float2*)(Cout + (size_t)(mA + 8) * N + c) =
                    make_float2(acc[mt][nt][2] + b0, acc[mt][nt][3] + b1);
            }
        }
    }
}

// ---------------------------------------------------------------------------
// Flash attention, HMMA hi/lo, cp.async double-buffered 128-key tiles.
// Block = 128 queries of one (b,h), 256 thr / 8 warps (warp owns 16 rows).
// smem (bytes): Qhi 0, Qlo 16384; stage s: Khi 32768+s*65536, Klo +16384,
// Vhi +32768, Vlo +49152. Total 160KB.
// ---------------------------------------------------------------------------
__global__ __launch_bounds__(256)
void flash2()
{
    extern __shared__ __align__(128) uint32_t sm[];
    const int tid = threadIdx.x, lane = tid & 31, w = tid >> 5;
    const int bh = blockIdx.y, b = bh >> 4, h = bh & 15;
    const int q0 = blockIdx.x * 128;
    const uint32_t base = smem_u32(sm);

    const int arow = lane & 15, aco = lane >> 4;
    const int brow = (lane & 7) | ((lane & 16) >> 1), bco = (lane & 8) >> 3;

    // Q preload (hi+lo): 2048 chunks
    #pragma unroll
    for (int it = 0; it < 8; it++) {
        int idx = tid + it * 256;
        int lohf = idx >= 1024;
        int row = (idx >> 3) & 127, ch = idx & 7;
        const uint32_t* sp = lohf ? g_qkvl : g_qkvh;
        const void* src = sp + ((size_t)bh * 2048 + q0 + row) * 32 + ch * 4;
        uint32_t dst = base + lohf * 16384 + row * 128 + ((ch ^ (row & 7)) * 16);
        cpa16(dst, src);
    }
    CP_COMMIT();

    auto issueKV = [&](int t) {
        int st = t & 1, s0 = t * 128;
        #pragma unroll
        for (int it = 0; it < 16; it++) {
            int idx = tid + it * 256;              // 0..4095
            int tensor = idx >> 11;                // 0=K, 1=V
            int lohf = (idx >> 10) & 1;
            int row = (idx >> 3) & 127, ch = idx & 7;
            const uint32_t* sp = lohf ? g_qkvl : g_qkvh;
            const void* src = sp + (size_t)(1 + tensor) * 2097152
                            + ((size_t)bh * 2048 + s0 + row) * 32 + ch * 4;
            uint32_t dst = base + 32768 + st * 65536 + tensor * 32768
                         + lohf * 16384 + row * 128 + ((ch ^ (row & 7)) * 16);
            cpa16(dst, src);
        }
    };

    issueKV(0); CP_COMMIT();

    float m_a = -1e30f, m_b = -1e30f, l_a = 0.f, l_b = 0.f;
    float o[8][4] = {};

    for (int t = 0; t < 16; t++) {
        if (t + 1 < 16) issueKV(t + 1);
        CP_COMMIT();
        CP_WAIT(1);
        __syncthreads();

        const uint32_t kBase = base + 32768 + (t & 1) * 65536;
        const uint32_t vBase = kBase + 32768;

        // S = Q K^T (Q pre-scaled by 0.125)
        float s[16][4] = {};
        #pragma unroll
        for (int kk = 0; kk < 4; kk++) {
            uint32_t aH[4], aL[4];
            {
                int r = w * 16 + arow;
                int c = (kk * 2 + aco) ^ (r & 7);
                ldsm4(aH, base + r * 128 + c * 16);
                ldsm4(aL, base + 16384 + r * 128 + c * 16);
            }
            #pragma unroll
            for (int g = 0; g < 8; g++) {
                int rb = g * 16 + brow;
                int cb = (kk * 2 + bco) ^ (rb & 7);
                uint32_t bHf[4], bLf[4];
                ldsm4(bHf, kBase + rb * 128 + cb * 16);
                ldsm4(bLf, kBase + 16384 + rb * 128 + cb * 16);
                mma_bf(s[2 * g],     aH, &bHf[0]);
                mma_bf(s[2 * g],     aH, &bLf[0]);
                mma_bf(s[2 * g],     aL, &bHf[0]);
                mma_bf(s[2 * g + 1], aH, &bHf[2]);
                mma_bf(s[2 * g + 1], aH, &bLf[2]);
                mma_bf(s[2 * g + 1], aL, &bHf[2]);
            }
        }

        // Online softmax (rows lane>>2 and +8; 4-lane group reduce)
        float mxa = -1e30f, mxb = -1e30f;
        #pragma unroll
        for (int nt = 0; nt < 16; nt++) {
            mxa = fmaxf(mxa, fmaxf(s[nt][0], s[nt][1]));
            mxb = fmaxf(mxb, fmaxf(s[nt][2], s[nt][3]));
        }
        mxa = fmaxf(mxa, __shfl_xor_sync(0xffffffffu, mxa, 1));
        mxa = fmaxf(mxa, __shfl_xor_sync(0xffffffffu, mxa, 2));
        mxb = fmaxf(mxb, __shfl_xor_sync(0xffffffffu, mxb, 1));
        mxb = fmaxf(mxb, __shfl_xor_sync(0xffffffffu, mxb, 2));
        float mna = fmaxf(m_a, mxa), mnb = fmaxf(m_b, mxb);
        float alA = __expf(m_a - mna), alB = __expf(m_b - mnb);
        m_a = mna; m_b = mnb;
        float suma = 0.f, sumb = 0.f;
        #pragma unroll
        for (int nt = 0; nt < 16; nt++) {
            s[nt][0] = __expf(s[nt][0] - mna); suma += s[nt][0];
            s[nt][1] = __expf(s[nt][1] - mna); suma += s[nt][1];
            s[nt][2] = __expf(s[nt][2] - mnb); sumb += s[nt][2];
            s[nt][3] = __expf(s[nt][3] - mnb); sumb += s[nt][3];
        }
        suma += __shfl_xor_sync(0xffffffffu, suma, 1);
        suma += __shfl_xor_sync(0xffffffffu, suma, 2);
        sumb += __shfl_xor_sync(0xffffffffu, sumb, 1);
        sumb += __shfl_xor_sync(0xffffffffu, sumb, 2);
        l_a = l_a * alA + suma;
        l_b = l_b * alB + sumb;
        #pragma unroll
        for (int dt = 0; dt < 8; dt++) {
            o[dt][0] *= alA; o[dt][1] *= alA;
            o[dt][2] *= alB; o[dt][3] *= alB;
        }

        // O += P V
        #pragma unroll
        for (int kc = 0; kc < 8; kc++) {
            uint32_t pH[4], pL[4];
            hilo2(s[2 * kc][0],     s[2 * kc][1],     pH[0], pL[0]);
            hilo2(s[2 * kc][2],     s[2 * kc][3],     pH[1], pL[1]);
            hilo2(s[2 * kc + 1][0], s[2 * kc + 1][1], pH[2], pL[2]);
            hilo2(s[2 * kc + 1][2], s[2 * kc + 1][3], pH[3], pL[3]);
            #pragma unroll
            for (int g = 0; g < 4; g++) {
                int rv = kc * 16 + arow;
                int cv = (g * 2 + aco) ^ (rv & 7);
                uint32_t vHf[4], vLf[4];
                ldsm4t(vHf, vBase + rv * 128 + cv * 16);
                ldsm4t(vLf, vBase + 16384 + rv * 128 + cv * 16);
                mma_bf(o[2 * g],     pH, &vHf[0]);
                mma_bf(o[2 * g],     pH, &vLf[0]);
                mma_bf(o[2 * g],     pL, &vHf[0]);
                mma_bf(o[2 * g + 1], pH, &vHf[2]);
                mma_bf(o[2 * g + 1], pH, &vLf[2]);
                mma_bf(o[2 * g + 1], pL, &vHf[2]);
            }
        }
        __syncthreads();
    }

    // Epilogue: normalize, pack hi/lo to g_aoh/g_aol [m][512]
    float ia = 1.f / l_a, ib = 1.f / l_b;
    size_t mA = (size_t)b * SEQ + q0 + w * 16 + (lane >> 2);
    #pragma unroll
    for (int dt = 0; dt < 8; dt++) {
        int c  = dt * 8 + (lane & 3) * 2;
        int ci = h * 32 + (c >> 1);
        uint32_t hh, ll;
        hilo2(o[dt][0] * ia, o[dt][1] * ia, hh, ll);
        g_aoh[mA * 512 + ci] = hh; g_aol[mA * 512 + ci] = ll;
        hilo2(o[dt][2] * ib, o[dt][3] * ib, hh, ll);
        g_aoh[(mA + 8) * 512 + ci] = hh; g_aol[(mA + 8) * 512 + ci] = ll;
    }
}

// ---------------------------------------------------------------------------
extern "C" void kernel_launch(void* const* d_in, const int* in_sizes, int n_in,
                              void* d_out, int out_size)
{
    const float* x      = (const float*)d_in[0];
    const float* w_qkv  = (const float*)d_in[1];
    const float* w_proj = (const float*)d_in[2];
    const float* b_proj = (const float*)d_in[3];
    float* out = (float*)d_out;

    void *pxh, *pxl, *pwqh, *pwql, *pwph, *pwpl, *pqh, *pql, *paoh, *paol;
    cudaGetSymbolAddress(&pxh, g_xh);   cudaGetSymbolAddress(&pxl, g_xl);
    cudaGetSymbolAddress(&pwqh, g_wqh); cudaGetSymbolAddress(&pwql, g_wql);
    cudaGetSymbolAddress(&pwph, g_wph); cudaGetSymbolAddress(&pwpl, g_wpl);
    cudaGetSymbolAddress(&pqh, g_qkvh); cudaGetSymbolAddress(&pql, g_qkvl);
    cudaGetSymbolAddress(&paoh, g_aoh); cudaGetSymbolAddress(&paol, g_aol);

    cudaFuncSetAttribute(mm2<0>, cudaFuncAttributeMaxDynamicSharedMemorySize, 98304);
    cudaFuncSetAttribute(mm2<1>, cudaFuncAttributeMaxDynamicSharedMemorySize, 98304);
    cudaFuncSetAttribute(flash2, cudaFuncAttributeMaxDynamicSharedMemorySize, 163840);

    // 1) Splits
    split_k<<<4096, 256>>>(x,      (uint32_t*)pxh,  (uint32_t*)pxl,  1048576);
    split_k<<<3072, 256>>>(w_qkv,  (uint32_t*)pwqh, (uint32_t*)pwql, 786432);
    split_k<<<1024, 256>>>(w_proj, (uint32_t*)pwph, (uint32_t*)pwpl, 262144);

    // 2) QKV projection -> split Q/K/V (Q scaled)
    mm2<0><<<dim3(24, 32), 256, 98304>>>(
        (uint32_t*)pxh, (uint32_t*)pxl, (uint32_t*)pwqh, (uint32_t*)pwql,
        nullptr, nullptr, (uint32_t*)pqh, (uint32_t*)pql, 3072, 1024);

    // 3) Attention
    flash2<<<dim3(16, 32), 256, 163840>>>();

    // 4) Output projection + bias
    mm2<1><<<dim3(8, 32), 256, 98304>>>(
        (uint32_t*)paoh, (uint32_t*)paol, (uint32_t*)pwph, (uint32_t*)pwpl,
        b_proj, out, nullptr, nullptr, 1024, 1024);
}

// round 5
// speedup vs baseline: 3.1535x; 1.0366x over previous
#include <cuda_runtime.h>
#include <cuda_bf16.h>
#include <cstdint>

#define DIM    1024
#define NHEADS 16
#define HDIM   64
#define BATCH  2
#define SEQ    2048
#define MROWS  4096

// ---------------------------------------------------------------------------
// Packed bf16 hi/lo global scratch (u32 = 2 bf16, k-major pairs)
// ---------------------------------------------------------------------------
__device__ __align__(128) uint32_t g_xh [MROWS * 512], g_xl [MROWS * 512];
__device__ __align__(128) uint32_t g_wqh[3072 * 512],  g_wql[3072 * 512];
__device__ __align__(128) uint32_t g_wph[1024 * 512],  g_wpl[1024 * 512];
// QKV: [s_idx(3)][bh(32)][seq(2048)][32 u32]   (Q pre-scaled by 0.125)
__device__ __align__(128) uint32_t g_qkvh[3u * 2097152], g_qkvl[3u * 2097152];
__device__ __align__(128) uint32_t g_aoh[MROWS * 512], g_aol[MROWS * 512];

// ---------------------------------------------------------------------------
// Helpers
// ---------------------------------------------------------------------------
__device__ __forceinline__ uint32_t smem_u32(const void* p) {
    uint32_t a;
    asm("{ .reg .u64 t; cvta.to.shared.u64 t, %1; cvt.u32.u64 %0, t; }" : "=r"(a) : "l"(p));
    return a;
}
__device__ __forceinline__ void ldsm4(uint32_t r[4], uint32_t addr) {
    asm volatile("ldmatrix.sync.aligned.m8n8.x4.shared.b16 {%0,%1,%2,%3}, [%4];"
                 : "=r"(r[0]), "=r"(r[1]), "=r"(r[2]), "=r"(r[3]) : "r"(addr));
}
__device__ __forceinline__ void ldsm4t(uint32_t r[4], uint32_t addr) {
    asm volatile("ldmatrix.sync.aligned.m8n8.x4.trans.shared.b16 {%0,%1,%2,%3}, [%4];"
                 : "=r"(r[0]), "=r"(r[1]), "=r"(r[2]), "=r"(r[3]) : "r"(addr));
}
__device__ __forceinline__ void mma_bf(float c[4], const uint32_t a[4], const uint32_t b[2]) {
    asm volatile(
        "mma.sync.aligned.m16n8k16.row.col.f32.bf16.bf16.f32 "
        "{%0,%1,%2,%3}, {%4,%5,%6,%7}, {%8,%9}, {%0,%1,%2,%3};"
        : "+f"(c[0]), "+f"(c[1]), "+f"(c[2]), "+f"(c[3])
        : "r"(a[0]), "r"(a[1]), "r"(a[2]), "r"(a[3]), "r"(b[0]), "r"(b[1]));
}
__device__ __forceinline__ uint32_t packbf(float x, float y) {
    unsigned short ux = __bfloat16_as_ushort(__float2bfloat16(x));
    unsigned short uy = __bfloat16_as_ushort(__float2bfloat16(y));
    return (uint32_t)ux | ((uint32_t)uy << 16);
}
__device__ __forceinline__ void hilo2(float x, float y, uint32_t& hi, uint32_t& lo) {
    float hx = __bfloat162float(__float2bfloat16(x));
    float hy = __bfloat162float(__float2bfloat16(y));
    hi = packbf(x, y);
    lo = packbf(x - hx, y - hy);
}
__device__ __forceinline__ void cpa16(uint32_t dst, const void* src) {
    asm volatile("cp.async.cg.shared.global [%0], [%1], 16;" :: "r"(dst), "l"(src));
}
#define CP_COMMIT() asm volatile("cp.async.commit_group;" ::: "memory")
#define CP_WAIT(n)  asm volatile("cp.async.wait_group %0;" :: "n"(n) : "memory")

// ---------------------------------------------------------------------------
// Split fp32 [rows][1024] -> packed hi/lo u32 [rows][512]
// ---------------------------------------------------------------------------
__global__ __launch_bounds__(256)
void split_k(const float* __restrict__ in, uint32_t* __restrict__ hi,
             uint32_t* __restrict__ lo, int n4)
{
    int g = blockIdx.x * 256 + threadIdx.x;
    if (g >= n4) return;
    float4 v = ((const float4*)in)[g];
    uint32_t h0, l0, h1, l1;
    hilo2(v.x, v.y, h0, l0);
    hilo2(v.z, v.w, h1, l1);
    ((uint2*)hi)[g] = make_uint2(h0, h1);
    ((uint2*)lo)[g] = make_uint2(l0, l1);
}

// ---------------------------------------------------------------------------
// GEMM: C[M,N] = A[M,K] @ B[N,K]^T, bf16 hi/lo 3-MMA, cp.async 3-stage.
// Block 128x128, BK=32, 512 thr (16 warps, 32x32 warp tile).
// smem/stage 32KB: A[128][128B] + B[128][128B]; row = 8x16B chunks
// (0-3 hi, 4-7 lo), phys chunk = logical ^ (row&7).
// EPI 0: split-store into g_qkvh/l (Q scaled by 0.125). EPI 1: fp32 + bias.
// ---------------------------------------------------------------------------
template <int EPI>
__global__ __launch_bounds__(512)
void mm2(const uint32_t* __restrict__ Ah, const uint32_t* __restrict__ Al,
         const uint32_t* __restrict__ Bh, const uint32_t* __restrict__ Bl,
         const float* __restrict__ bias, float* __restrict__ Cout,
         uint32_t* __restrict__ qh, uint32_t* __restrict__ ql,
         int N, int K)
{
    extern __shared__ __align__(128) uint32_t sm[];
    const int tid = threadIdx.x, lane = tid & 31, wid = tid >> 5;
    const int m0 = blockIdx.y * 128, n0 = blockIdx.x * 128;
    const int wm = (wid & 3) * 32, wn = (wid >> 2) * 32;
    const uint32_t base = smem_u32(sm);
    const int T  = K >> 5;
    const int KC = K >> 3;   // 16B chunks per row

    const int arow = lane & 15, aco = lane >> 4;
    const int brow = (lane & 7) | ((lane & 16) >> 1), bco = (lane & 8) >> 3;

    auto issue = [&](int t) {
        int st  = t % 3;
        int kc0 = t << 2;
        #pragma unroll
        for (int it = 0; it < 4; it++) {
            int idx = tid + it * 512;              // 0..2047 (A first, then B)
            int row = (idx >> 3) & 127;
            int ch  = idx & 7;
            bool isB = idx >= 1024;
            const uint32_t* sp = isB ? (ch < 4 ? Bh : Bl) : (ch < 4 ? Ah : Al);
            int grow = (isB ? n0 : m0) + row;
            const void* src = sp + ((size_t)grow * KC + kc0 + (ch & 3)) * 4;
            uint32_t dst = base + st * 32768 + (isB ? 16384 : 0)
                         + row * 128 + ((ch ^ (row & 7)) * 16);
            cpa16(dst, src);
        }
    };

    float acc[2][4][4] = {};

    issue(0); CP_COMMIT();
    issue(1); CP_COMMIT();

    for (int t = 0; t < T; t++) {
        if (t + 2 < T) { issue(t + 2); CP_COMMIT(); CP_WAIT(2); }
        else           { CP_WAIT(0); }
        __syncthreads();

        const uint32_t aOff = base + (t % 3) * 32768;
        const uint32_t bOff = aOff + 16384;
        #pragma unroll
        for (int kk = 0; kk < 2; kk++) {
            uint32_t aH[2][4], aL[2][4], bH[2][4], bL[2][4];
            #pragma unroll
            for (int mt = 0; mt < 2; mt++) {
                int r = wm + mt * 16 + arow;
                int c = (kk * 2 + aco) ^ (r & 7);
                ldsm4(aH[mt], aOff + r * 128 + c * 16);
                ldsm4(aL[mt], aOff + r * 128 + (c ^ 4) * 16);
            }
            #pragma unroll
            for (int g = 0; g < 2; g++) {
                int r = wn + g * 16 + brow;
                int c = (kk * 2 + bco) ^ (r & 7);
                ldsm4(bH[g], bOff + r * 128 + c * 16);
                ldsm4(bL[g], bOff + r * 128 + (c ^ 4) * 16);
            }
            #pragma unroll
            for (int mt = 0; mt < 2; mt++)
                #pragma unroll
                for (int nt = 0; nt < 4; nt++) {
                    const uint32_t* bh = &bH[nt >> 1][(nt & 1) * 2];
                    const uint32_t* bl = &bL[nt >> 1][(nt & 1) * 2];
                    mma_bf(acc[mt][nt], aH[mt], bh);
                    mma_bf(acc[mt][nt], aH[mt], bl);
                    mma_bf(acc[mt][nt], aL[mt], bh);
                }
        }
        __syncthreads();
    }

    const int r = lane >> 2, j = (lane & 3) * 2;
    if (EPI == 0) {
        const int sidx = n0 >> 10;
        const float qs = (sidx == 0) ? 0.125f : 1.0f;
        uint32_t* H = qh + (size_t)sidx * 2097152;
        uint32_t* L = ql + (size_t)sidx * 2097152;
        #pragma unroll
        for (int mt = 0; mt < 2; mt++) {
            int mA = m0 + wm + mt * 16 + r;
            int b  = mA >> 11, q = mA & 2047;
            #pragma unroll
            for (int nt = 0; nt < 4; nt++) {
                int n = n0 + wn + nt * 8 + j;
                int rin = n & 1023, h = rin >> 6, d = rin & 63;
                size_t o1 = (((size_t)(b * 16 + h)) * 2048 + q) * 32 + (d >> 1);
                uint32_t hh, ll;
                hilo2(acc[mt][nt][0] * qs, acc[mt][nt][1] * qs, hh, ll);
                H[o1] = hh; L[o1] = ll;
                hilo2(acc[mt][nt][2] * qs, acc[mt][nt][3] * qs, hh, ll);
                H[o1 + 8 * 32] = hh; L[o1 + 8 * 32] = ll;
            }
        }
    } else {
        #pragma unroll
        for (int mt = 0; mt < 2; mt++) {
            int mA = m0 + wm + mt * 16 + r;
            #pragma unroll
            for (int nt = 0; nt < 4; nt++) {
                int c = n0 + wn + nt * 8 + j;
                float b0 = bias[c], b1 = bias[c + 1];
                *(float2*)(Cout + (size_t)mA * N + c) =
                    make_float2(acc[mt][nt][0] + b0, acc[mt][nt][1] + b1);
                *(float2*)(Cout + (size_t)(mA + 8) * N + c) =
                    make_float2(acc[mt][nt][2] + b0, acc[mt][nt][3] + b1);
            }
        }
    }
}

// ---------------------------------------------------------------------------
// Flash attention, HMMA hi/lo, cp.async double-buffered 64-key tiles.
// Block = 256 queries of one (b,h), 512 thr / 16 warps (warp owns 16 rows).
// smem (bytes): Qhi 0 (32KB), Qlo 32768; stage s at 65536+s*32768:
//   Khi +0 (8KB), Klo +8192, Vhi +16384, Vlo +24576.  Total 128KB.
// ---------------------------------------------------------------------------
__global__ __launch_bounds__(512)
void flash2()
{
    extern __shared__ __align__(128) uint32_t sm[];
    const int tid = threadIdx.x, lane = tid & 31, w = tid >> 5;
    const int bh = blockIdx.y, b = bh >> 4, h = bh & 15;
    const int q0 = blockIdx.x * 256;
    const uint32_t base = smem_u32(sm);

    const int arow = lane & 15, aco = lane >> 4;
    const int brow = (lane & 7) | ((lane & 16) >> 1), bco = (lane & 8) >> 3;

    // Q preload (hi+lo): 4096 16B-chunks
    #pragma unroll
    for (int it = 0; it < 8; it++) {
        int idx = tid + it * 512;
        int lohf = idx >= 2048;
        int row = (idx >> 3) & 255, ch = idx & 7;
        const uint32_t* sp = lohf ? g_qkvl : g_qkvh;
        const void* src = sp + ((size_t)bh * 2048 + q0 + row) * 32 + ch * 4;
        uint32_t dst = base + lohf * 32768 + row * 128 + ((ch ^ (row & 7)) * 16);
        cpa16(dst, src);
    }
    CP_COMMIT();

    auto issueKV = [&](int t) {
        int st = t & 1, s0 = t * 64;
        #pragma unroll
        for (int it = 0; it < 4; it++) {
            int idx = tid + it * 512;              // 0..2047
            int tensor = idx >> 10;                // 0=K, 1=V
            int lohf = (idx >> 9) & 1;
            int row = (idx >> 3) & 63, ch = idx & 7;
            const uint32_t* sp = lohf ? g_qkvl : g_qkvh;
            const void* src = sp + (size_t)(1 + tensor) * 2097152
                            + ((size_t)bh * 2048 + s0 + row) * 32 + ch * 4;
            uint32_t dst = base + 65536 + st * 32768 + tensor * 16384
                         + lohf * 8192 + row * 128 + ((ch ^ (row & 7)) * 16);
            cpa16(dst, src);
        }
    };

    issueKV(0); CP_COMMIT();

    float m_a = -1e30f, m_b = -1e30f, l_a = 0.f, l_b = 0.f;
    float o[8][4] = {};

    const int NT = SEQ / 64;   // 32
    for (int t = 0; t < NT; t++) {
        if (t + 1 < NT) { issueKV(t + 1); CP_COMMIT(); CP_WAIT(1); }
        else            { CP_WAIT(0); }
        __syncthreads();

        const uint32_t kBase = base + 65536 + (t & 1) * 32768;
        const uint32_t vBase = kBase + 16384;

        // S = Q K^T (Q pre-scaled by 0.125). 64 keys = 8 n8 tiles.
        float s[8][4] = {};
        #pragma unroll
        for (int kk = 0; kk < 4; kk++) {
            uint32_t aH[4], aL[4];
            {
                int r = w * 16 + arow;
                int c = (kk * 2 + aco) ^ (r & 7);
                ldsm4(aH, base + r * 128 + c * 16);
                ldsm4(aL, base + 32768 + r * 128 + c * 16);
            }
            #pragma unroll
            for (int g = 0; g < 4; g++) {
                int rb = g * 16 + brow;
                int cb = (kk * 2 + bco) ^ (rb & 7);
                uint32_t bHf[4], bLf[4];
                ldsm4(bHf, kBase + rb * 128 + cb * 16);
                ldsm4(bLf, kBase + 8192 + rb * 128 + cb * 16);
                mma_bf(s[2 * g],     aH, &bHf[0]);
                mma_bf(s[2 * g],     aH, &bLf[0]);
                mma_bf(s[2 * g],     aL, &bHf[0]);
                mma_bf(s[2 * g + 1], aH, &bHf[2]);
                mma_bf(s[2 * g + 1], aH, &bLf[2]);
                mma_bf(s[2 * g + 1], aL, &bHf[2]);
            }
        }

        // Online softmax (rows lane>>2 and +8; 4-lane group reduce)
        float mxa = -1e30f, mxb = -1e30f;
        #pragma unroll
        for (int nt = 0; nt < 8; nt++) {
            mxa = fmaxf(mxa, fmaxf(s[nt][0], s[nt][1]));
            mxb = fmaxf(mxb, fmaxf(s[nt][2], s[nt][3]));
        }
        mxa = fmaxf(mxa, __shfl_xor_sync(0xffffffffu, mxa, 1));
        mxa = fmaxf(mxa, __shfl_xor_sync(0xffffffffu, mxa, 2));
        mxb = fmaxf(mxb, __shfl_xor_sync(0xffffffffu, mxb, 1));
        mxb = fmaxf(mxb, __shfl_xor_sync(0xffffffffu, mxb, 2));
        float mna = fmaxf(m_a, mxa), mnb = fmaxf(m_b, mxb);
        float alA = __expf(m_a - mna), alB = __expf(m_b - mnb);
        m_a = mna; m_b = mnb;
        float suma = 0.f, sumb = 0.f;
        #pragma unroll
        for (int nt = 0; nt < 8; nt++) {
            s[nt][0] = __expf(s[nt][0] - mna); suma += s[nt][0];
            s[nt][1] = __expf(s[nt][1] - mna); suma += s[nt][1];
            s[nt][2] = __expf(s[nt][2] - mnb); sumb += s[nt][2];
            s[nt][3] = __expf(s[nt][3] - mnb); sumb += s[nt][3];
        }
        suma += __shfl_xor_sync(0xffffffffu, suma, 1);
        suma += __shfl_xor_sync(0xffffffffu, suma, 2);
        sumb += __shfl_xor_sync(0xffffffffu, sumb, 1);
        sumb += __shfl_xor_sync(0xffffffffu, sumb, 2);
        l_a = l_a * alA + suma;
        l_b = l_b * alB + sumb;
        #pragma unroll
        for (int dt = 0; dt < 8; dt++) {
            o[dt][0] *= alA; o[dt][1] *= alA;
            o[dt][2] *= alB; o[dt][3] *= alB;
        }

        // O += P V  (kc = 4 key-chunks of 16; dt = 8 d-tiles)
        #pragma unroll
        for (int kc = 0; kc < 4; kc++) {
            uint32_t pH[4], pL[4];
            hilo2(s[2 * kc][0],     s[2 * kc][1],     pH[0], pL[0]);
            hilo2(s[2 * kc][2],     s[2 * kc][3],     pH[1], pL[1]);
            hilo2(s[2 * kc + 1][0], s[2 * kc + 1][1], pH[2], pL[2]);
            hilo2(s[2 * kc + 1][2], s[2 * kc + 1][3], pH[3], pL[3]);
            #pragma unroll
            for (int g = 0; g < 4; g++) {
                int rv = kc * 16 + arow;
                int cv = (g * 2 + aco) ^ (rv & 7);
                uint32_t vHf[4], vLf[4];
                ldsm4t(vHf, vBase + rv * 128 + cv * 16);
                ldsm4t(vLf, vBase + 8192 + rv * 128 + cv * 16);
                mma_bf(o[2 * g],     pH, &vHf[0]);
                mma_bf(o[2 * g],     pH, &vLf[0]);
                mma_bf(o[2 * g],     pL, &vHf[0]);
                mma_bf(o[2 * g + 1], pH, &vHf[2]);
                mma_bf(o[2 * g + 1], pH, &vLf[2]);
                mma_bf(o[2 * g + 1], pL, &vHf[2]);
            }
        }
        __syncthreads();
    }

    // Epilogue: normalize, pack hi/lo to g_aoh/g_aol [m][512]
    float ia = 1.f / l_a, ib = 1.f / l_b;
    size_t mA = (size_t)b * SEQ + q0 + w * 16 + (lane >> 2);
    #pragma unroll
    for (int dt = 0; dt < 8; dt++) {
        int c  = dt * 8 + (lane & 3) * 2;
        int ci = h * 32 + (c >> 1);
        uint32_t hh, ll;
        hilo2(o[dt][0] * ia, o[dt][1] * ia, hh, ll);
        g_aoh[mA * 512 + ci] = hh; g_aol[mA * 512 + ci] = ll;
        hilo2(o[dt][2] * ib, o[dt][3] * ib, hh, ll);
        g_aoh[(mA + 8) * 512 + ci] = hh; g_aol[(mA + 8) * 512 + ci] = ll;
    }
}

// ---------------------------------------------------------------------------
extern "C" void kernel_launch(void* const* d_in, const int* in_sizes, int n_in,
                              void* d_out, int out_size)
{
    const float* x      = (const float*)d_in[0];
    const float* w_qkv  = (const float*)d_in[1];
    const float* w_proj = (const float*)d_in[2];
    const float* b_proj = (const float*)d_in[3];
    float* out = (float*)d_out;

    void *pxh, *pxl, *pwqh, *pwql, *pwph, *pwpl, *pqh, *pql, *paoh, *paol;
    cudaGetSymbolAddress(&pxh, g_xh);   cudaGetSymbolAddress(&pxl, g_xl);
    cudaGetSymbolAddress(&pwqh, g_wqh); cudaGetSymbolAddress(&pwql, g_wql);
    cudaGetSymbolAddress(&pwph, g_wph); cudaGetSymbolAddress(&pwpl, g_wpl);
    cudaGetSymbolAddress(&pqh, g_qkvh); cudaGetSymbolAddress(&pql, g_qkvl);
    cudaGetSymbolAddress(&paoh, g_aoh); cudaGetSymbolAddress(&paol, g_aol);

    cudaFuncSetAttribute(mm2<0>, cudaFuncAttributeMaxDynamicSharedMemorySize, 98304);
    cudaFuncSetAttribute(mm2<1>, cudaFuncAttributeMaxDynamicSharedMemorySize, 98304);
    cudaFuncSetAttribute(flash2, cudaFuncAttributeMaxDynamicSharedMemorySize, 131072);

    // 1) Splits
    split_k<<<4096, 256>>>(x,      (uint32_t*)pxh,  (uint32_t*)pxl,  1048576);
    split_k<<<3072, 256>>>(w_qkv,  (uint32_t*)pwqh, (uint32_t*)pwql, 786432);
    split_k<<<1024, 256>>>(w_proj, (uint32_t*)pwph, (uint32_t*)pwpl, 262144);

    // 2) QKV projection -> split Q/K/V (Q scaled)
    mm2<0><<<dim3(24, 32), 512, 98304>>>(
        (uint32_t*)pxh, (uint32_t*)pxl, (uint32_t*)pwqh, (uint32_t*)pwql,
        nullptr, nullptr, (uint32_t*)pqh, (uint32_t*)pql, 3072, 1024);

    // 3) Attention: 256 queries/block per (b,h)
    flash2<<<dim3(8, 32), 512, 131072>>>();

    // 4) Output projection + bias
    mm2<1><<<dim3(8, 32), 512, 98304>>>(
        (uint32_t*)paoh, (uint32_t*)paol, (uint32_t*)pwph, (uint32_t*)pwpl,
        b_proj, out, nullptr, nullptr, 1024, 1024);
}

// round 6
// speedup vs baseline: 3.2976x; 1.0457x over previous
#include <cuda_runtime.h>
#include <cuda_bf16.h>
#include <cstdint>

#define DIM    1024
#define NHEADS 16
#define HDIM   64
#define BATCH  2
#define SEQ    2048
#define MROWS  4096

// ---------------------------------------------------------------------------
// Packed bf16 hi/lo global scratch (u32 = 2 bf16, k-major pairs)
// ---------------------------------------------------------------------------
__device__ __align__(128) uint32_t g_xh [MROWS * 512], g_xl [MROWS * 512];
__device__ __align__(128) uint32_t g_wqh[3072 * 512],  g_wql[3072 * 512];
__device__ __align__(128) uint32_t g_wph[1024 * 512],  g_wpl[1024 * 512];
// QKV: [s_idx(3)][bh(32)][seq(2048)][32 u32]   (Q pre-scaled by 0.125)
__device__ __align__(128) uint32_t g_qkvh[3u * 2097152], g_qkvl[3u * 2097152];
__device__ __align__(128) uint32_t g_aoh[MROWS * 512], g_aol[MROWS * 512];

// ---------------------------------------------------------------------------
// Helpers
// ---------------------------------------------------------------------------
__device__ __forceinline__ uint32_t smem_u32(const void* p) {
    uint32_t a;
    asm("{ .reg .u64 t; cvta.to.shared.u64 t, %1; cvt.u32.u64 %0, t; }" : "=r"(a) : "l"(p));
    return a;
}
__device__ __forceinline__ void ldsm4(uint32_t r[4], uint32_t addr) {
    asm volatile("ldmatrix.sync.aligned.m8n8.x4.shared.b16 {%0,%1,%2,%3}, [%4];"
                 : "=r"(r[0]), "=r"(r[1]), "=r"(r[2]), "=r"(r[3]) : "r"(addr));
}
__device__ __forceinline__ void ldsm4t(uint32_t r[4], uint32_t addr) {
    asm volatile("ldmatrix.sync.aligned.m8n8.x4.trans.shared.b16 {%0,%1,%2,%3}, [%4];"
                 : "=r"(r[0]), "=r"(r[1]), "=r"(r[2]), "=r"(r[3]) : "r"(addr));
}
__device__ __forceinline__ void mma_bf(float c[4], const uint32_t a[4], const uint32_t b[2]) {
    asm volatile(
        "mma.sync.aligned.m16n8k16.row.col.f32.bf16.bf16.f32 "
        "{%0,%1,%2,%3}, {%4,%5,%6,%7}, {%8,%9}, {%0,%1,%2,%3};"
        : "+f"(c[0]), "+f"(c[1]), "+f"(c[2]), "+f"(c[3])
        : "r"(a[0]), "r"(a[1]), "r"(a[2]), "r"(a[3]), "r"(b[0]), "r"(b[1]));
}
__device__ __forceinline__ uint32_t packbf(float x, float y) {
    unsigned short ux = __bfloat16_as_ushort(__float2bfloat16(x));
    unsigned short uy = __bfloat16_as_ushort(__float2bfloat16(y));
    return (uint32_t)ux | ((uint32_t)uy << 16);
}
__device__ __forceinline__ void hilo2(float x, float y, uint32_t& hi, uint32_t& lo) {
    float hx = __bfloat162float(__float2bfloat16(x));
    float hy = __bfloat162float(__float2bfloat16(y));
    hi = packbf(x, y);
    lo = packbf(x - hx, y - hy);
}
__device__ __forceinline__ void cpa16(uint32_t dst, const void* src) {
    asm volatile("cp.async.cg.shared.global [%0], [%1], 16;" :: "r"(dst), "l"(src));
}
#define CP_COMMIT() asm volatile("cp.async.commit_group;" ::: "memory")
#define CP_WAIT(n)  asm volatile("cp.async.wait_group %0;" :: "n"(n) : "memory")

// ---------------------------------------------------------------------------
// Split fp32 [rows][1024] -> packed hi/lo u32 [rows][512]
// ---------------------------------------------------------------------------
__global__ __launch_bounds__(256)
void split_k(const float* __restrict__ in, uint32_t* __restrict__ hi,
             uint32_t* __restrict__ lo, int n4)
{
    int g = blockIdx.x * 256 + threadIdx.x;
    if (g >= n4) return;
    float4 v = ((const float4*)in)[g];
    uint32_t h0, l0, h1, l1;
    hilo2(v.x, v.y, h0, l0);
    hilo2(v.z, v.w, h1, l1);
    ((uint2*)hi)[g] = make_uint2(h0, h1);
    ((uint2*)lo)[g] = make_uint2(l0, l1);
}

// ---------------------------------------------------------------------------
// GEMM: C[M,N] = A[M,K] @ B[N,K]^T, bf16 hi/lo 3-MMA, cp.async 3-stage BK=64.
// Block 128x128, 512 thr (16 warps, 32x32 warp tile).
// smem/stage 64KB: Ahi[128][128B] +0, Alo +16K, Bhi +32K, Blo +48K.
// Row = 8x16B chunks, phys chunk = logical ^ (row&7).
// EPI 0: split-store into g_qkvh/l (Q scaled by 0.125). EPI 1: fp32 + bias.
// ---------------------------------------------------------------------------
template <int EPI>
__global__ __launch_bounds__(512)
void mm2(const uint32_t* __restrict__ Ah, const uint32_t* __restrict__ Al,
         const uint32_t* __restrict__ Bh, const uint32_t* __restrict__ Bl,
         const float* __restrict__ bias, float* __restrict__ Cout,
         uint32_t* __restrict__ qh, uint32_t* __restrict__ ql,
         int N, int K)
{
    extern __shared__ __align__(128) uint32_t sm[];
    const int tid = threadIdx.x, lane = tid & 31, wid = tid >> 5;
    const int m0 = blockIdx.y * 128, n0 = blockIdx.x * 128;
    const int wm = (wid & 3) * 32, wn = (wid >> 2) * 32;
    const uint32_t base = smem_u32(sm);
    const int T  = K >> 6;   // k64 steps
    const int KC = K >> 3;   // 16B chunks per row

    const int arow = lane & 15, aco = lane >> 4;
    const int brow = (lane & 7) | ((lane & 16) >> 1), bco = (lane & 8) >> 3;

    auto issue = [&](int t) {
        int st  = t % 3;
        int kc0 = t << 3;                          // 8 chunks per k64
        #pragma unroll
        for (int it = 0; it < 8; it++) {
            int idx = tid + it * 512;              // 0..4095
            int blk = idx >> 10;                   // 0 Ahi, 1 Alo, 2 Bhi, 3 Blo
            int row = (idx >> 3) & 127;
            int ch  = idx & 7;
            const uint32_t* sp = (blk == 0) ? Ah : (blk == 1) ? Al
                               : (blk == 2) ? Bh : Bl;
            int grow = ((blk >> 1) ? n0 : m0) + row;
            const void* src = sp + ((size_t)grow * KC + kc0 + ch) * 4;
            uint32_t dst = base + st * 65536 + blk * 16384
                         + row * 128 + ((ch ^ (row & 7)) * 16);
            cpa16(dst, src);
        }
    };

    float acc[2][4][4] = {};

    issue(0); CP_COMMIT();
    issue(1); CP_COMMIT();

    for (int t = 0; t < T; t++) {
        if (t + 2 < T) { issue(t + 2); CP_COMMIT(); CP_WAIT(2); }
        else           { CP_WAIT(0); }
        __syncthreads();

        const uint32_t sOff = base + (t % 3) * 65536;
        #pragma unroll
        for (int kk = 0; kk < 4; kk++) {
            uint32_t aH[2][4], aL[2][4], bH[2][4], bL[2][4];
            #pragma unroll
            for (int mt = 0; mt < 2; mt++) {
                int r = wm + mt * 16 + arow;
                int c = (kk * 2 + aco) ^ (r & 7);
                ldsm4(aH[mt], sOff + r * 128 + c * 16);
                ldsm4(aL[mt], sOff + 16384 + r * 128 + c * 16);
            }
            #pragma unroll
            for (int g = 0; g < 2; g++) {
                int r = wn + g * 16 + brow;
                int c = (kk * 2 + bco) ^ (r & 7);
                ldsm4(bH[g], sOff + 32768 + r * 128 + c * 16);
                ldsm4(bL[g], sOff + 49152 + r * 128 + c * 16);
            }
            #pragma unroll
            for (int mt = 0; mt < 2; mt++)
                #pragma unroll
                for (int nt = 0; nt < 4; nt++) {
                    const uint32_t* bh = &bH[nt >> 1][(nt & 1) * 2];
                    const uint32_t* bl = &bL[nt >> 1][(nt & 1) * 2];
                    mma_bf(acc[mt][nt], aH[mt], bh);
                    mma_bf(acc[mt][nt], aH[mt], bl);
                    mma_bf(acc[mt][nt], aL[mt], bh);
                }
        }
        __syncthreads();
    }

    const int r = lane >> 2, j = (lane & 3) * 2;
    if (EPI == 0) {
        const int sidx = n0 >> 10;
        const float qs = (sidx == 0) ? 0.125f : 1.0f;
        uint32_t* H = qh + (size_t)sidx * 2097152;
        uint32_t* L = ql + (size_t)sidx * 2097152;
        #pragma unroll
        for (int mt = 0; mt < 2; mt++) {
            int mA = m0 + wm + mt * 16 + r;
            int b  = mA >> 11, q = mA & 2047;
            #pragma unroll
            for (int nt = 0; nt < 4; nt++) {
                int n = n0 + wn + nt * 8 + j;
                int rin = n & 1023, h = rin >> 6, d = rin & 63;
                size_t o1 = (((size_t)(b * 16 + h)) * 2048 + q) * 32 + (d >> 1);
                uint32_t hh, ll;
                hilo2(acc[mt][nt][0] * qs, acc[mt][nt][1] * qs, hh, ll);
                H[o1] = hh; L[o1] = ll;
                hilo2(acc[mt][nt][2] * qs, acc[mt][nt][3] * qs, hh, ll);
                H[o1 + 8 * 32] = hh; L[o1 + 8 * 32] = ll;
            }
        }
    } else {
        #pragma unroll
        for (int mt = 0; mt < 2; mt++) {
            int mA = m0 + wm + mt * 16 + r;
            #pragma unroll
            for (int nt = 0; nt < 4; nt++) {
                int c = n0 + wn + nt * 8 + j;
                float b0 = bias[c], b1 = bias[c + 1];
                *(float2*)(Cout + (size_t)mA * N + c) =
                    make_float2(acc[mt][nt][0] + b0, acc[mt][nt][1] + b1);
                *(float2*)(Cout + (size_t)(mA + 8) * N + c) =
                    make_float2(acc[mt][nt][2] + b0, acc[mt][nt][3] + b1);
            }
        }
    }
}

// ---------------------------------------------------------------------------
// Flash attention, HMMA hi/lo, cp.async 3-stage 64-key KV ring (1 sync/iter).
// Block = 256 queries of one (b,h), 512 thr / 16 warps (warp owns 16 rows).
// smem (bytes): Qhi 0 (32KB), Qlo 32768; KV stage s at 65536+s*32768:
//   Khi +0, Klo +8192, Vhi +16384, Vlo +24576.  Total 160KB.
// ---------------------------------------------------------------------------
__global__ __launch_bounds__(512)
void flash2()
{
    extern __shared__ __align__(128) uint32_t sm[];
    const int tid = threadIdx.x, lane = tid & 31, w = tid >> 5;
    const int bh = blockIdx.y, b = bh >> 4, h = bh & 15;
    const int q0 = blockIdx.x * 256;
    const uint32_t base = smem_u32(sm);

    const int arow = lane & 15, aco = lane >> 4;
    const int brow = (lane & 7) | ((lane & 16) >> 1), bco = (lane & 8) >> 3;

    // Q preload (hi+lo): 4096 16B-chunks
    #pragma unroll
    for (int it = 0; it < 8; it++) {
        int idx = tid + it * 512;
        int lohf = idx >= 2048;
        int row = (idx >> 3) & 255, ch = idx & 7;
        const uint32_t* sp = lohf ? g_qkvl : g_qkvh;
        const void* src = sp + ((size_t)bh * 2048 + q0 + row) * 32 + ch * 4;
        uint32_t dst = base + lohf * 32768 + row * 128 + ((ch ^ (row & 7)) * 16);
        cpa16(dst, src);
    }
    CP_COMMIT();

    auto issueKV = [&](int t) {
        int st = t % 3, s0 = t * 64;
        #pragma unroll
        for (int it = 0; it < 4; it++) {
            int idx = tid + it * 512;              // 0..2047
            int tensor = idx >> 10;                // 0=K, 1=V
            int lohf = (idx >> 9) & 1;
            int row = (idx >> 3) & 63, ch = idx & 7;
            const uint32_t* sp = lohf ? g_qkvl : g_qkvh;
            const void* src = sp + (size_t)(1 + tensor) * 2097152
                            + ((size_t)bh * 2048 + s0 + row) * 32 + ch * 4;
            uint32_t dst = base + 65536 + st * 32768 + tensor * 16384
                         + lohf * 8192 + row * 128 + ((ch ^ (row & 7)) * 16);
            cpa16(dst, src);
        }
    };

    issueKV(0); CP_COMMIT();

    float m_a = -1e30f, m_b = -1e30f, l_a = 0.f, l_b = 0.f;
    float o[8][4] = {};

    const int NT = SEQ / 64;   // 32
    for (int t = 0; t < NT; t++) {
        if (t + 1 < NT) { issueKV(t + 1); CP_COMMIT(); CP_WAIT(1); }
        else            { CP_WAIT(0); }
        __syncthreads();

        const uint32_t kBase = base + 65536 + (t % 3) * 32768;
        const uint32_t vBase = kBase + 16384;

        // S = Q K^T (Q pre-scaled by 0.125). 64 keys = 8 n8 tiles.
        float s[8][4] = {};
        #pragma unroll
        for (int kk = 0; kk < 4; kk++) {
            uint32_t aH[4], aL[4];
            {
                int r = w * 16 + arow;
                int c = (kk * 2 + aco) ^ (r & 7);
                ldsm4(aH, base + r * 128 + c * 16);
                ldsm4(aL, base + 32768 + r * 128 + c * 16);
            }
            #pragma unroll
            for (int g = 0; g < 4; g++) {
                int rb = g * 16 + brow;
                int cb = (kk * 2 + bco) ^ (rb & 7);
                uint32_t bHf[4], bLf[4];
                ldsm4(bHf, kBase + rb * 128 + cb * 16);
                ldsm4(bLf, kBase + 8192 + rb * 128 + cb * 16);
                mma_bf(s[2 * g],     aH, &bHf[0]);
                mma_bf(s[2 * g],     aH, &bLf[0]);
                mma_bf(s[2 * g],     aL, &bHf[0]);
                mma_bf(s[2 * g + 1], aH, &bHf[2]);
                mma_bf(s[2 * g + 1], aH, &bLf[2]);
                mma_bf(s[2 * g + 1], aL, &bHf[2]);
            }
        }

        // Online softmax (rows lane>>2 and +8; 4-lane group reduce)
        float mxa = -1e30f, mxb = -1e30f;
        #pragma unroll
        for (int nt = 0; nt < 8; nt++) {
            mxa = fmaxf(mxa, fmaxf(s[nt][0], s[nt][1]));
            mxb = fmaxf(mxb, fmaxf(s[nt][2], s[nt][3]));
        }
        mxa = fmaxf(mxa, __shfl_xor_sync(0xffffffffu, mxa, 1));
        mxa = fmaxf(mxa, __shfl_xor_sync(0xffffffffu, mxa, 2));
        mxb = fmaxf(mxb, __shfl_xor_sync(0xffffffffu, mxb, 1));
        mxb = fmaxf(mxb, __shfl_xor_sync(0xffffffffu, mxb, 2));
        float mna = fmaxf(m_a, mxa), mnb = fmaxf(m_b, mxb);
        float alA = __expf(m_a - mna), alB = __expf(m_b - mnb);
        m_a = mna; m_b = mnb;
        float suma = 0.f, sumb = 0.f;
        #pragma unroll
        for (int nt = 0; nt < 8; nt++) {
            s[nt][0] = __expf(s[nt][0] - mna); suma += s[nt][0];
            s[nt][1] = __expf(s[nt][1] - mna); suma += s[nt][1];
            s[nt][2] = __expf(s[nt][2] - mnb); sumb += s[nt][2];
            s[nt][3] = __expf(s[nt][3] - mnb); sumb += s[nt][3];
        }
        suma += __shfl_xor_sync(0xffffffffu, suma, 1);
        suma += __shfl_xor_sync(0xffffffffu, suma, 2);
        sumb += __shfl_xor_sync(0xffffffffu, sumb, 1);
        sumb += __shfl_xor_sync(0xffffffffu, sumb, 2);
        l_a = l_a * alA + suma;
        l_b = l_b * alB + sumb;
        #pragma unroll
        for (int dt = 0; dt < 8; dt++) {
            o[dt][0] *= alA; o[dt][1] *= alA;
            o[dt][2] *= alB; o[dt][3] *= alB;
        }

        // O += P V  (kc = 4 key-chunks of 16; dt = 8 d-tiles)
        #pragma unroll
        for (int kc = 0; kc < 4; kc++) {
            uint32_t pH[4], pL[4];
            hilo2(s[2 * kc][0],     s[2 * kc][1],     pH[0], pL[0]);
            hilo2(s[2 * kc][2],     s[2 * kc][3],     pH[1], pL[1]);
            hilo2(s[2 * kc + 1][0], s[2 * kc + 1][1], pH[2], pL[2]);
            hilo2(s[2 * kc + 1][2], s[2 * kc + 1][3], pH[3], pL[3]);
            #pragma unroll
            for (int g = 0; g < 4; g++) {
                int rv = kc * 16 + arow;
                int cv = (g * 2 + aco) ^ (rv & 7);
                uint32_t vHf[4], vLf[4];
                ldsm4t(vHf, vBase + rv * 128 + cv * 16);
                ldsm4t(vLf, vBase + 8192 + rv * 128 + cv * 16);
                mma_bf(o[2 * g],     pH, &vHf[0]);
                mma_bf(o[2 * g],     pH, &vLf[0]);
                mma_bf(o[2 * g],     pL, &vHf[0]);
                mma_bf(o[2 * g + 1], pH, &vHf[2]);
                mma_bf(o[2 * g + 1], pH, &vLf[2]);
                mma_bf(o[2 * g + 1], pL, &vHf[2]);
            }
        }
        // NOTE: no bottom barrier — 3-stage KV ring makes it safe.
    }

    // Epilogue: normalize, pack hi/lo to g_aoh/g_aol [m][512]
    float ia = 1.f / l_a, ib = 1.f / l_b;
    size_t mA = (size_t)b * SEQ + q0 + w * 16 + (lane >> 2);
    #pragma unroll
    for (int dt = 0; dt < 8; dt++) {
        int c  = dt * 8 + (lane & 3) * 2;
        int ci = h * 32 + (c >> 1);
        uint32_t hh, ll;
        hilo2(o[dt][0] * ia, o[dt][1] * ia, hh, ll);
        g_aoh[mA * 512 + ci] = hh; g_aol[mA * 512 + ci] = ll;
        hilo2(o[dt][2] * ib, o[dt][3] * ib, hh, ll);
        g_aoh[(mA + 8) * 512 + ci] = hh; g_aol[(mA + 8) * 512 + ci] = ll;
    }
}

// ---------------------------------------------------------------------------
extern "C" void kernel_launch(void* const* d_in, const int* in_sizes, int n_in,
                              void* d_out, int out_size)
{
    const float* x      = (const float*)d_in[0];
    const float* w_qkv  = (const float*)d_in[1];
    const float* w_proj = (const float*)d_in[2];
    const float* b_proj = (const float*)d_in[3];
    float* out = (float*)d_out;

    void *pxh, *pxl, *pwqh, *pwql, *pwph, *pwpl, *pqh, *pql, *paoh, *paol;
    cudaGetSymbolAddress(&pxh, g_xh);   cudaGetSymbolAddress(&pxl, g_xl);
    cudaGetSymbolAddress(&pwqh, g_wqh); cudaGetSymbolAddress(&pwql, g_wql);
    cudaGetSymbolAddress(&pwph, g_wph); cudaGetSymbolAddress(&pwpl, g_wpl);
    cudaGetSymbolAddress(&pqh, g_qkvh); cudaGetSymbolAddress(&pql, g_qkvl);
    cudaGetSymbolAddress(&paoh, g_aoh); cudaGetSymbolAddress(&paol, g_aol);

    cudaFuncSetAttribute(mm2<0>, cudaFuncAttributeMaxDynamicSharedMemorySize, 196608);
    cudaFuncSetAttribute(mm2<1>, cudaFuncAttributeMaxDynamicSharedMemorySize, 196608);
    cudaFuncSetAttribute(flash2, cudaFuncAttributeMaxDynamicSharedMemorySize, 163840);

    // 1) Splits
    split_k<<<4096, 256>>>(x,      (uint32_t*)pxh,  (uint32_t*)pxl,  1048576);
    split_k<<<3072, 256>>>(w_qkv,  (uint32_t*)pwqh, (uint32_t*)pwql, 786432);
    split_k<<<1024, 256>>>(w_proj, (uint32_t*)pwph, (uint32_t*)pwpl, 262144);

    // 2) QKV projection -> split Q/K/V (Q scaled)
    mm2<0><<<dim3(24, 32), 512, 196608>>>(
        (uint32_t*)pxh, (uint32_t*)pxl, (uint32_t*)pwqh, (uint32_t*)pwql,
        nullptr, nullptr, (uint32_t*)pqh, (uint32_t*)pql, 3072, 1024);

    // 3) Attention: 256 queries/block per (b,h)
    flash2<<<dim3(8, 32), 512, 163840>>>();

    // 4) Output projection + bias
    mm2<1><<<dim3(8, 32), 512, 196608>>>(
        (uint32_t*)paoh, (uint32_t*)paol, (uint32_t*)pwph, (uint32_t*)pwpl,
        b_proj, out, nullptr, nullptr, 1024, 1024);
}